// round 2
// baseline (speedup 1.0000x reference)
#include <cuda_runtime.h>

// HashTables: rolling xor-hash over prefix windows {1,2,4,...,128}, then gather
// 8 embedding rows (64 f32 each) per (b,t) into out[b][t][8*64].
//
// Math reduction: BUCKETS = 2^19 (power of two) and the hash is a XOR of
// nonnegative int64 products, so  h % BUCKETS == h & 0x7FFFF, and only the low
// 32 bits of each token*prime product matter -> pure u32 arithmetic.
// A zero token contributes 0 to the XOR, so the t-1-j < 0 boundary is handled
// by zero-padding the shared token halo (branch-free inner loop).
//
// NOTE: the harness materializes the int64 tokens input as int32 (its dtype
// set is {float32, int32, bf16}); tokens < 32000 fit losslessly.

#define T_LEN   4096
#define B_ROWS  8
#define P_TILE  64          // t-positions per block
#define NTHR    256
#define HALO    128
#define MASK19  0x7FFFFu

static __device__ __forceinline__ unsigned prime_of(int j) {
    // j is a compile-time constant under full unroll -> immediates in SASS
    const unsigned PR[8] = {2654435761u, 2246822519u, 3266489917u, 2028178513u,
                            1220703125u, 1610612741u, 805306457u, 402653189u};
    return PR[j & 7];
}

__global__ __launch_bounds__(NTHR)
void hash_gather_kernel(const int* __restrict__ tokens,         // [B][T] int32
                        const float* __restrict__ tables,       // [8][2^19][64] f32
                        float* __restrict__ out)                // [B][T][512] f32
{
    __shared__ unsigned s_tok[P_TILE + HALO];   // 192 u32
    __shared__ unsigned s_idx[P_TILE * 8];      // bucket ids per (pos, table)

    const int tid = threadIdx.x;
    const int b  = blockIdx.y;
    const int t0 = blockIdx.x * P_TILE;

    // ---- Phase 0: stage tokens, zero-pad before row start ----
    if (tid < P_TILE + HALO) {
        int g = t0 - HALO + tid;
        s_tok[tid] = (g >= 0) ? (unsigned)tokens[(size_t)b * T_LEN + g] : 0u;
    }
    __syncthreads();

    // ---- Phase 1: rolling hash, snapshot at each power-of-two window ----
    if (tid < P_TILE) {
        unsigned h = 0;
        int w = 0;
        #pragma unroll
        for (int j = 0; j < 128; j++) {
            // position s = t-1-j -> local index tid + 127 - j (always in [0,192))
            h ^= s_tok[tid + (HALO - 1) - j] * prime_of(j);
            const int off = j + 1;
            if ((off & (off - 1)) == 0) {       // off in {1,2,4,...,128}
                s_idx[tid * 8 + w] = h & MASK19;
                w++;
            }
        }
    }
    __syncthreads();

    // ---- Phase 2: gather + write. One float4 per (pos, table, f4) element.
    // 16 consecutive threads cover one 256B table row; writes are contiguous.
    const size_t out_base_f4 = ((size_t)b * T_LEN + t0) << 7;   // *128 float4s per pos
    const float4* __restrict__ tab4 = (const float4*)tables;
    float4* __restrict__ out4 = (float4*)out;

    #pragma unroll 4
    for (int e = tid; e < P_TILE * 128; e += NTHR) {
        const int rest = e & 127;       // within-position element
        const int p    = e >> 7;        // local position
        const int tbl  = rest >> 4;     // table id 0..7
        const int f4   = rest & 15;     // float4 within 64-float row
        const unsigned idx = s_idx[p * 8 + tbl];
        // tables[tbl][idx][:] -> 16 float4s
        const float4 v = __ldg(tab4 + ((((size_t)tbl << 19) + idx) << 4) + f4);
        out4[out_base_f4 + e] = v;
    }
}

extern "C" void kernel_launch(void* const* d_in, const int* in_sizes, int n_in,
                              void* d_out, int out_size) {
    const int* tokens   = (const int*)d_in[0];
    const float* tables = (const float*)d_in[1];
    float* out          = (float*)d_out;

    dim3 grid(T_LEN / P_TILE, B_ROWS);   // (64, 8)
    hash_gather_kernel<<<grid, NTHR>>>(tokens, tables, out);
}

// round 3
// speedup vs baseline: 1.2183x; 1.2183x over previous
#include <cuda_runtime.h>

// HashTables: rolling xor-hash over prefix windows {1,2,4,...,128}, then gather
// 8 embedding rows (64 f32 each) per (b,t) into out[b][t][8*64].
//
// Math reduction: BUCKETS = 2^19 (power of two) and the hash is a XOR of
// nonnegative int64 products, so  h % BUCKETS == h & 0x7FFFF, and only the low
// 32 bits of each token*prime product matter -> pure u32 arithmetic.
// A zero token contributes 0 to the XOR, so the t-1-j < 0 boundary is handled
// by zero-padding the shared token halo (branch-free inner loop).
//
// R2 -> R3: latency-bound at occ=38.9% (grid-limited). Halve P_TILE to double
// the grid (1024 blocks, ~78% occ) and use evict-first (.cs) output stores to
// keep table rows resident in L2.

#define T_LEN   4096
#define B_ROWS  8
#define P_TILE  32          // t-positions per block
#define NTHR    256
#define HALO    128
#define MASK19  0x7FFFFu

static __device__ __forceinline__ unsigned prime_of(int j) {
    const unsigned PR[8] = {2654435761u, 2246822519u, 3266489917u, 2028178513u,
                            1220703125u, 1610612741u, 805306457u, 402653189u};
    return PR[j & 7];
}

static __device__ __forceinline__ void stg_cs_f4(float4* p, float4 v) {
    asm volatile("st.global.cs.v4.f32 [%0], {%1, %2, %3, %4};"
                 :: "l"(p), "f"(v.x), "f"(v.y), "f"(v.z), "f"(v.w) : "memory");
}

__global__ __launch_bounds__(NTHR)
void hash_gather_kernel(const int* __restrict__ tokens,         // [B][T] int32
                        const float* __restrict__ tables,       // [8][2^19][64] f32
                        float* __restrict__ out)                // [B][T][512] f32
{
    __shared__ unsigned s_tok[P_TILE + HALO];   // 160 u32
    __shared__ unsigned s_idx[P_TILE * 8];      // bucket ids per (pos, table)

    const int tid = threadIdx.x;
    const int b  = blockIdx.y;
    const int t0 = blockIdx.x * P_TILE;

    // ---- Phase 0: stage tokens, zero-pad before row start ----
    if (tid < P_TILE + HALO) {
        int g = t0 - HALO + tid;
        s_tok[tid] = (g >= 0) ? (unsigned)tokens[(size_t)b * T_LEN + g] : 0u;
    }
    __syncthreads();

    // ---- Phase 1: rolling hash, snapshot at each power-of-two window ----
    if (tid < P_TILE) {
        unsigned h = 0;
        int w = 0;
        #pragma unroll
        for (int j = 0; j < 128; j++) {
            // position s = t-1-j -> local index tid + 127 - j (always in [0,160))
            h ^= s_tok[tid + (HALO - 1) - j] * prime_of(j);
            const int off = j + 1;
            if ((off & (off - 1)) == 0) {       // off in {1,2,4,...,128}
                s_idx[tid * 8 + w] = h & MASK19;
                w++;
            }
        }
    }
    __syncthreads();

    // ---- Phase 2: gather + write. One float4 per (pos, table, f4) element.
    // 16 consecutive threads cover one 256B table row; writes are contiguous.
    const size_t out_base_f4 = ((size_t)b * T_LEN + t0) << 7;   // *128 float4s per pos
    const float4* __restrict__ tab4 = (const float4*)tables;
    float4* __restrict__ out4 = (float4*)out;

    #pragma unroll 4
    for (int e = tid; e < P_TILE * 128; e += NTHR) {
        const int rest = e & 127;       // within-position element
        const int p    = e >> 7;        // local position
        const int tbl  = rest >> 4;     // table id 0..7
        const int f4   = rest & 15;     // float4 within 64-float row
        const unsigned idx = s_idx[p * 8 + tbl];
        const float4 v = __ldg(tab4 + ((((size_t)tbl << 19) + idx) << 4) + f4);
        stg_cs_f4(out4 + out_base_f4 + e, v);
    }
}

extern "C" void kernel_launch(void* const* d_in, const int* in_sizes, int n_in,
                              void* d_out, int out_size) {
    const int* tokens   = (const int*)d_in[0];
    const float* tables = (const float*)d_in[1];
    float* out          = (float*)d_out;

    dim3 grid(T_LEN / P_TILE, B_ROWS);   // (128, 8)
    hash_gather_kernel<<<grid, NTHR>>>(tokens, tables, out);
}